// round 1
// baseline (speedup 1.0000x reference)
#include <cuda_runtime.h>
#include <math.h>

// ---------------- problem constants ----------------
#define Bc    128
#define BUFFc 64
#define STKc  48
#define HISTc 96
#define FCc   128
#define Uc    256
#define NOUTc 82
#define WDIMc 300
#define POSDc 50
#define EDINc 350     // WDIM + POSD
#define CADc  50
#define HADc  50
#define RDINc 306     // FC + CAD + FC

// ---------------- device scratch (no allocations allowed) ----------------
__device__ float g_buff_emb[Bc * BUFFc * FCc];          // 4 MB
__device__ float g_comp_emb[Bc * STKc * 16 * FCc];      // 50 MB
__device__ float g_stack_emb[Bc * STKc * FCc];          // 3 MB

__device__ float g_c0[3][Bc * Uc];
__device__ float g_c1[3][Bc * Uc];
__device__ float g_h0[3][2][Bc * Uc];
__device__ float g_h1[3][2][Bc * Uc];

__device__ __forceinline__ float sigm(float x) { return 1.0f / (1.0f + expf(-x)); }

// ---------------- embedding: relu([w_emb[id], p_emb[pid]] @ emb_W + b) ----------------
// 8 rows per block, 128 threads; thread j computes output column j for 8 rows.
__global__ void embed_kernel(const int* __restrict__ word_ids,
                             const int* __restrict__ pos_ids,
                             const float* __restrict__ w_emb,
                             const float* __restrict__ p_emb,
                             const float* __restrict__ W,     // (350,128)
                             const float* __restrict__ bias,  // (128)
                             float* __restrict__ out,         // (nrows,128)
                             int nrows) {
    __shared__ float xs[8][EDINc];
    __shared__ int wid_s[8], pid_s[8];
    const int r0 = blockIdx.x * 8;
    const int tid = threadIdx.x;

    if (tid < 8) {
        int row = r0 + tid;
        wid_s[tid] = (row < nrows) ? word_ids[row] : 0;
        pid_s[tid] = (row < nrows) ? pos_ids[row] : 0;
    }
    __syncthreads();

    for (int idx = tid; idx < 8 * EDINc; idx += 128) {
        int r = idx / EDINc, k = idx - r * EDINc;
        float v;
        if (k < WDIMc) v = w_emb[wid_s[r] * WDIMc + k];
        else           v = p_emb[pid_s[r] * POSDc + (k - WDIMc)];
        xs[r][k] = v;
    }
    __syncthreads();

    float acc[8];
    const float bj = bias[tid];
#pragma unroll
    for (int r = 0; r < 8; r++) acc[r] = bj;

#pragma unroll 2
    for (int k = 0; k < EDINc; k++) {
        float w = W[k * FCc + tid];
#pragma unroll
        for (int r = 0; r < 8; r++) acc[r] = fmaf(xs[r][k], w, acc[r]);
    }
#pragma unroll
    for (int r = 0; r < 8; r++) {
        int row = r0 + r;
        if (row < nrows) out[row * FCc + tid] = fmaxf(acc[r], 0.0f);
    }
}

// ---------------- compose: recursive tree composition per (b, stk) ----------------
// One block per sequence (6144 blocks), 128 threads; 8 sequential steps.
__global__ void compose_kernel(const int* __restrict__ comp_word_id,   // (B*STK*16)
                               const float* __restrict__ comp_emb,     // (B*STK*16,128)
                               const int* __restrict__ comp_action_id, // (B*STK*8)
                               const int* __restrict__ comp_action_len,// (B*STK)
                               const float* __restrict__ a_emb,        // (80,50)
                               const float* __restrict__ rec_W,        // (306,128)
                               const float* __restrict__ rec_b,        // (128)
                               float* __restrict__ stack_emb) {        // (B*STK,128)
    const int seq = blockIdx.x;
    const int tid = threadIdx.x;
    __shared__ float vals[8][FCc];
    __shared__ float xbuf[RDINc];
    __shared__ int hid[8], did[8];

    if (tid < 8) {
        hid[tid] = comp_word_id[seq * 16 + 2 * tid];
        did[tid] = comp_word_id[seq * 16 + 2 * tid + 1];
    }
    __syncthreads();

    const float bj = rec_b[tid];
    for (int n = 0; n < 8; n++) {
        int ih = -1, idd = -1;
        for (int m = 0; m < n; m++) {
            if (hid[m] == hid[n]) ih = m;
            if (hid[m] == did[n]) idd = m;
        }
        float he = (ih  >= 0) ? vals[ih][tid]  : comp_emb[(seq * 16 + 2 * n) * FCc + tid];
        float de = (idd >= 0) ? vals[idd][tid] : comp_emb[(seq * 16 + 2 * n + 1) * FCc + tid];
        xbuf[tid] = he;
        xbuf[FCc + CADc + tid] = de;
        if (tid < CADc) xbuf[FCc + tid] = a_emb[comp_action_id[seq * 8 + n] * CADc + tid];
        __syncthreads();

        float acc = bj;
#pragma unroll 2
        for (int k = 0; k < RDINc; k++) acc = fmaf(xbuf[k], rec_W[k * FCc + tid], acc);
        vals[n][tid] = tanhf(acc);
        __syncthreads();
    }

    int al = comp_action_len[seq];
    float outv = (al == 0) ? comp_emb[(seq * 16) * FCc + tid] : vals[al - 1][tid];
    stack_emb[seq * FCc + tid] = outv;
}

// ---------------- one LSTM layer timestep ----------------
// z = [x_t, h_prev] @ W + b ; gates ; masked state update (fused epilogue).
// Grid (32, 8): 8 u-columns x 4 gates per block (32 z-cols), 16 batches per block.
// mode 0: x[(b*T+t)*Din + k]    mode 1: x[b*256 + k]    mode 2: gather table[ids[b*T+t]]
__global__ void lstm_step_kernel(const float* __restrict__ x_base,
                                 const int*   __restrict__ gather_ids,
                                 const float* __restrict__ gather_tab,
                                 int mode, int Din, int T, int t,
                                 const float* __restrict__ W,     // (Din+256, 1024)
                                 const float* __restrict__ bias,  // (1024)
                                 const int*   __restrict__ lengths,
                                 const float* __restrict__ h_prev,// (B,256)
                                 float*       __restrict__ c,     // (B,256) in-place
                                 float*       __restrict__ h_next)// (B,256)
{
    const int Dtot = Din + Uc;
    __shared__ float xs[16][512];
    __shared__ float zs[32][17];
    const int tid = threadIdx.x;           // 256
    const int b0 = blockIdx.y * 16;
    const int u0 = blockIdx.x * 8;

    // stage [x_t, h_prev] for 16 batches
    const int total = 16 * Dtot;
    for (int idx = tid; idx < total; idx += 256) {
        int bl = idx / Dtot, k = idx - bl * Dtot;
        int b = b0 + bl;
        float v;
        if (k < Din) {
            if (mode == 0)      v = x_base[(b * T + t) * Din + k];
            else if (mode == 1) v = x_base[b * Uc + k];
            else                v = gather_tab[gather_ids[b * T + t] * Din + k];
        } else {
            v = h_prev[b * Uc + (k - Din)];
        }
        xs[bl][k] = v;
    }
    __syncthreads();

    const int col = tid & 31;
    const int u   = col & 7;
    const int g   = col >> 3;
    const int bl0 = tid >> 5;               // 0..7
    const int gcol = g * Uc + u0 + u;

    float a0 = bias[gcol], a1 = a0;
    const float* Wc = W + gcol;
#pragma unroll 8
    for (int k = 0; k < Dtot; k++) {
        float w = Wc[k * 1024];
        a0 = fmaf(xs[bl0][k], w, a0);
        a1 = fmaf(xs[bl0 + 8][k], w, a1);
    }
    zs[col][bl0]     = a0;
    zs[col][bl0 + 8] = a1;
    __syncthreads();

    if (tid < 128) {
        const int uu = tid & 7;
        const int bl = tid >> 3;            // 0..15
        float iv = zs[uu][bl];
        float jv = zs[8 + uu][bl];
        float fv = zs[16 + uu][bl];
        float ov = zs[24 + uu][bl];
        const int b = b0 + bl;
        const int idx = b * Uc + (u0 + uu);
        const bool m = (t < lengths[b]);
        float cold = c[idx];
        float cn = cold * sigm(fv + 1.0f) + sigm(iv) * tanhf(jv);
        float hn = tanhf(cn) * sigm(ov);
        if (m) { c[idx] = cn; h_next[idx] = hn; }
        else   { h_next[idx] = h_prev[idx]; }
    }
}

// ---------------- output head ----------------
__global__ void final_kernel(const float* __restrict__ hs,
                             const float* __restrict__ hb,
                             const float* __restrict__ ha,
                             const float* __restrict__ fW,  // (768, 82)
                             const float* __restrict__ fb,  // (82)
                             float* __restrict__ out) {     // (B, 82)
    const int b = blockIdx.x;
    const int tid = threadIdx.x; // 128
    __shared__ float hcat[3 * Uc];
    for (int idx = tid; idx < 3 * Uc; idx += 128) {
        float v;
        if (idx < Uc)            v = hs[b * Uc + idx];
        else if (idx < 2 * Uc)   v = hb[b * Uc + idx - Uc];
        else                     v = ha[b * Uc + idx - 2 * Uc];
        hcat[idx] = v;
    }
    __syncthreads();
    if (tid < NOUTc) {
        float acc = fb[tid];
#pragma unroll 2
        for (int k = 0; k < 3 * Uc; k++) acc = fmaf(hcat[k], fW[k * NOUTc + tid], acc);
        out[b * NOUTc + tid] = acc;
    }
}

// ---------------- host driver ----------------
static void run_lstm(const float* x_base, const int* gather_ids, const float* gather_tab,
                     int mode, int Din, int T,
                     const float* W0, const float* b0,
                     const float* W1, const float* b1,
                     const int* lengths,
                     float* c0, float* h0a, float* h0b,
                     float* c1, float* h1a, float* h1b) {
    dim3 grid(32, 8);
    float* h0buf[2] = { h0a, h0b };
    float* h1buf[2] = { h1a, h1b };
    for (int t = 0; t < T; t++) {
        const float* h0p = h0buf[t & 1];
        float*       h0n = h0buf[(t + 1) & 1];
        lstm_step_kernel<<<grid, 256>>>(x_base, gather_ids, gather_tab, mode, Din, T, t,
                                        W0, b0, lengths, h0p, c0, h0n);
        const float* h1p = h1buf[t & 1];
        float*       h1n = h1buf[(t + 1) & 1];
        lstm_step_kernel<<<grid, 256>>>(h0n, nullptr, nullptr, 1, Uc, T, t,
                                        W1, b1, lengths, h1p, c1, h1n);
    }
}

extern "C" void kernel_launch(void* const* d_in, const int* in_sizes, int n_in,
                              void* d_out, int out_size) {
    const int*   buff_word_id   = (const int*)d_in[0];
    const int*   buff_pos_id    = (const int*)d_in[1];
    const int*   comp_word_id   = (const int*)d_in[2];
    const int*   comp_pos_id    = (const int*)d_in[3];
    const int*   comp_action_id = (const int*)d_in[4];
    const int*   comp_action_len= (const int*)d_in[5];
    const int*   history_action_id = (const int*)d_in[6];
    const int*   stack_length   = (const int*)d_in[7];
    const int*   buff_length    = (const int*)d_in[8];
    const int*   history_action_length = (const int*)d_in[9];
    const float* p_emb      = (const float*)d_in[10];
    const float* comp_a_emb = (const float*)d_in[11];
    const float* hist_a_emb = (const float*)d_in[12];
    const float* w_emb      = (const float*)d_in[13];
    const float* emb_W      = (const float*)d_in[14];
    const float* emb_b      = (const float*)d_in[15];
    const float* rec_W      = (const float*)d_in[16];
    const float* rec_b      = (const float*)d_in[17];
    const float* sW0 = (const float*)d_in[18];
    const float* sb0 = (const float*)d_in[19];
    const float* sW1 = (const float*)d_in[20];
    const float* sb1 = (const float*)d_in[21];
    const float* bW0 = (const float*)d_in[22];
    const float* bb0 = (const float*)d_in[23];
    const float* bW1 = (const float*)d_in[24];
    const float* bb1 = (const float*)d_in[25];
    const float* aW0 = (const float*)d_in[26];
    const float* ab0 = (const float*)d_in[27];
    const float* aW1 = (const float*)d_in[28];
    const float* ab1 = (const float*)d_in[29];
    const float* fW  = (const float*)d_in[30];
    const float* fb  = (const float*)d_in[31];
    float* out = (float*)d_out;

    float *buff_emb_p, *comp_emb_p, *stack_emb_p;
    float *c0_p, *c1_p, *h0_p, *h1_p;
    cudaGetSymbolAddress((void**)&buff_emb_p,  g_buff_emb);
    cudaGetSymbolAddress((void**)&comp_emb_p,  g_comp_emb);
    cudaGetSymbolAddress((void**)&stack_emb_p, g_stack_emb);
    cudaGetSymbolAddress((void**)&c0_p, g_c0);
    cudaGetSymbolAddress((void**)&c1_p, g_c1);
    cudaGetSymbolAddress((void**)&h0_p, g_h0);
    cudaGetSymbolAddress((void**)&h1_p, g_h1);

    const size_t SB = (size_t)Bc * Uc;   // floats per state buffer

    // zero initial states (graph-capturable memsets)
    cudaMemsetAsync(c0_p, 0, 3 * SB * sizeof(float));
    cudaMemsetAsync(c1_p, 0, 3 * SB * sizeof(float));
    cudaMemsetAsync(h0_p, 0, 3 * 2 * SB * sizeof(float));
    cudaMemsetAsync(h1_p, 0, 3 * 2 * SB * sizeof(float));

    // embeddings
    const int nbuff = Bc * BUFFc;
    embed_kernel<<<(nbuff + 7) / 8, 128>>>(buff_word_id, buff_pos_id, w_emb, p_emb,
                                           emb_W, emb_b, buff_emb_p, nbuff);
    const int ncomp = Bc * STKc * 16;
    embed_kernel<<<(ncomp + 7) / 8, 128>>>(comp_word_id, comp_pos_id, w_emb, p_emb,
                                           emb_W, emb_b, comp_emb_p, ncomp);

    // recursive compose -> stack_emb
    compose_kernel<<<Bc * STKc, 128>>>(comp_word_id, comp_emb_p, comp_action_id,
                                       comp_action_len, comp_a_emb, rec_W, rec_b,
                                       stack_emb_p);

    // three 2-layer LSTMs (sequential on one stream; overlap is a later round)
    // lstm 0: stack  (T=48, Din=128)
    run_lstm(stack_emb_p, nullptr, nullptr, 0, FCc, STKc,
             sW0, sb0, sW1, sb1, stack_length,
             c0_p + 0 * SB, h0_p + (0 * 2 + 0) * SB, h0_p + (0 * 2 + 1) * SB,
             c1_p + 0 * SB, h1_p + (0 * 2 + 0) * SB, h1_p + (0 * 2 + 1) * SB);
    // lstm 1: buffer (T=64, Din=128)
    run_lstm(buff_emb_p, nullptr, nullptr, 0, FCc, BUFFc,
             bW0, bb0, bW1, bb1, buff_length,
             c0_p + 1 * SB, h0_p + (1 * 2 + 0) * SB, h0_p + (1 * 2 + 1) * SB,
             c1_p + 1 * SB, h1_p + (1 * 2 + 0) * SB, h1_p + (1 * 2 + 1) * SB);
    // lstm 2: action (T=96, Din=50, gathered from hist_a_emb)
    run_lstm(nullptr, history_action_id, hist_a_emb, 2, HADc, HISTc,
             aW0, ab0, aW1, ab1, history_action_length,
             c0_p + 2 * SB, h0_p + (2 * 2 + 0) * SB, h0_p + (2 * 2 + 1) * SB,
             c1_p + 2 * SB, h1_p + (2 * 2 + 0) * SB, h1_p + (2 * 2 + 1) * SB);

    // output head: final h1 lives in buffer 0 for T = 48 / 64 / 96 (all even)
    final_kernel<<<Bc, 128>>>(h1_p + (0 * 2 + 0) * SB,
                              h1_p + (1 * 2 + 0) * SB,
                              h1_p + (2 * 2 + 0) * SB,
                              fW, fb, out);
}

// round 2
// speedup vs baseline: 1.0329x; 1.0329x over previous
#include <cuda_runtime.h>
#include <math.h>

// ---------------- problem constants ----------------
#define Bc    128
#define BUFFc 64
#define STKc  48
#define HISTc 96
#define FCc   128
#define Uc    256
#define NOUTc 82
#define WDIMc 300
#define POSDc 50
#define EDINc 350     // WDIM + POSD
#define CADc  50
#define HADc  50
#define RDINc 306     // FC + CAD + FC

// ---------------- device scratch (no allocations allowed) ----------------
__device__ float g_buff_emb[Bc * BUFFc * FCc];          // 4 MB
__device__ float g_comp_emb[Bc * STKc * 16 * FCc];      // 50 MB
__device__ float g_stack_emb[Bc * STKc * FCc];          // 3 MB

__device__ float g_c0[3][Bc * Uc];
__device__ float g_c1[3][Bc * Uc];
__device__ float g_h0[3][2][Bc * Uc];
__device__ float g_h1[3][2][Bc * Uc];

__device__ __forceinline__ float sigm(float x) { return 1.0f / (1.0f + expf(-x)); }

// ---------------- embedding: relu([w_emb[id], p_emb[pid]] @ emb_W + b) ----------------
// 8 rows per block, 128 threads; thread j computes output column j for 8 rows.
__global__ void embed_kernel(const int* __restrict__ word_ids,
                             const int* __restrict__ pos_ids,
                             const float* __restrict__ w_emb,
                             const float* __restrict__ p_emb,
                             const float* __restrict__ W,     // (350,128)
                             const float* __restrict__ bias,  // (128)
                             float* __restrict__ out,         // (nrows,128)
                             int nrows) {
    __shared__ float xs[8][EDINc];
    __shared__ int wid_s[8], pid_s[8];
    const int r0 = blockIdx.x * 8;
    const int tid = threadIdx.x;

    if (tid < 8) {
        int row = r0 + tid;
        wid_s[tid] = (row < nrows) ? word_ids[row] : 0;
        pid_s[tid] = (row < nrows) ? pos_ids[row] : 0;
    }
    __syncthreads();

    for (int idx = tid; idx < 8 * EDINc; idx += 128) {
        int r = idx / EDINc, k = idx - r * EDINc;
        float v;
        if (k < WDIMc) v = w_emb[wid_s[r] * WDIMc + k];
        else           v = p_emb[pid_s[r] * POSDc + (k - WDIMc)];
        xs[r][k] = v;
    }
    __syncthreads();

    float acc[8];
    const float bj = bias[tid];
#pragma unroll
    for (int r = 0; r < 8; r++) acc[r] = bj;

#pragma unroll 2
    for (int k = 0; k < EDINc; k++) {
        float w = W[k * FCc + tid];
#pragma unroll
        for (int r = 0; r < 8; r++) acc[r] = fmaf(xs[r][k], w, acc[r]);
    }
#pragma unroll
    for (int r = 0; r < 8; r++) {
        int row = r0 + r;
        if (row < nrows) out[row * FCc + tid] = fmaxf(acc[r], 0.0f);
    }
}

// ---------------- compose: recursive tree composition per (b, stk) ----------------
// One block per sequence (6144 blocks), 128 threads; 8 sequential steps.
__global__ void compose_kernel(const int* __restrict__ comp_word_id,   // (B*STK*16)
                               const float* __restrict__ comp_emb,     // (B*STK*16,128)
                               const int* __restrict__ comp_action_id, // (B*STK*8)
                               const int* __restrict__ comp_action_len,// (B*STK)
                               const float* __restrict__ a_emb,        // (80,50)
                               const float* __restrict__ rec_W,        // (306,128)
                               const float* __restrict__ rec_b,        // (128)
                               float* __restrict__ stack_emb) {        // (B*STK,128)
    const int seq = blockIdx.x;
    const int tid = threadIdx.x;
    __shared__ float vals[8][FCc];
    __shared__ float xbuf[RDINc];
    __shared__ int hid[8], did[8];

    if (tid < 8) {
        hid[tid] = comp_word_id[seq * 16 + 2 * tid];
        did[tid] = comp_word_id[seq * 16 + 2 * tid + 1];
    }
    __syncthreads();

    const float bj = rec_b[tid];
    for (int n = 0; n < 8; n++) {
        int ih = -1, idd = -1;
        for (int m = 0; m < n; m++) {
            if (hid[m] == hid[n]) ih = m;
            if (hid[m] == did[n]) idd = m;
        }
        float he = (ih  >= 0) ? vals[ih][tid]  : comp_emb[(seq * 16 + 2 * n) * FCc + tid];
        float de = (idd >= 0) ? vals[idd][tid] : comp_emb[(seq * 16 + 2 * n + 1) * FCc + tid];
        xbuf[tid] = he;
        xbuf[FCc + CADc + tid] = de;
        if (tid < CADc) xbuf[FCc + tid] = a_emb[comp_action_id[seq * 8 + n] * CADc + tid];
        __syncthreads();

        float acc = bj;
#pragma unroll 2
        for (int k = 0; k < RDINc; k++) acc = fmaf(xbuf[k], rec_W[k * FCc + tid], acc);
        vals[n][tid] = tanhf(acc);
        __syncthreads();
    }

    int al = comp_action_len[seq];
    float outv = (al == 0) ? comp_emb[(seq * 16) * FCc + tid] : vals[al - 1][tid];
    stack_emb[seq * FCc + tid] = outv;
}

// ---------------- one LSTM layer timestep ----------------
// z = [x_t, h_prev] @ W + b ; gates ; masked state update (fused epilogue).
// Grid (32, 8): 8 u-columns x 4 gates per block (32 z-cols), 16 batches per block.
// mode 0: x[(b*T+t)*Din + k]    mode 1: x[b*256 + k]    mode 2: gather table[ids[b*T+t]]
__global__ void lstm_step_kernel(const float* __restrict__ x_base,
                                 const int*   __restrict__ gather_ids,
                                 const float* __restrict__ gather_tab,
                                 int mode, int Din, int T, int t,
                                 const float* __restrict__ W,     // (Din+256, 1024)
                                 const float* __restrict__ bias,  // (1024)
                                 const int*   __restrict__ lengths,
                                 const float* __restrict__ h_prev,// (B,256)
                                 float*       __restrict__ c,     // (B,256) in-place
                                 float*       __restrict__ h_next)// (B,256)
{
    const int Dtot = Din + Uc;
    __shared__ float xs[16][512];
    __shared__ float zs[32][17];
    const int tid = threadIdx.x;           // 256
    const int b0 = blockIdx.y * 16;
    const int u0 = blockIdx.x * 8;

    // stage [x_t, h_prev] for 16 batches
    const int total = 16 * Dtot;
    for (int idx = tid; idx < total; idx += 256) {
        int bl = idx / Dtot, k = idx - bl * Dtot;
        int b = b0 + bl;
        float v;
        if (k < Din) {
            if (mode == 0)      v = x_base[(b * T + t) * Din + k];
            else if (mode == 1) v = x_base[b * Uc + k];
            else                v = gather_tab[gather_ids[b * T + t] * Din + k];
        } else {
            v = h_prev[b * Uc + (k - Din)];
        }
        xs[bl][k] = v;
    }
    __syncthreads();

    const int col = tid & 31;
    const int u   = col & 7;
    const int g   = col >> 3;
    const int bl0 = tid >> 5;               // 0..7
    const int gcol = g * Uc + u0 + u;

    float a0 = bias[gcol], a1 = a0;
    const float* Wc = W + gcol;
#pragma unroll 8
    for (int k = 0; k < Dtot; k++) {
        float w = Wc[k * 1024];
        a0 = fmaf(xs[bl0][k], w, a0);
        a1 = fmaf(xs[bl0 + 8][k], w, a1);
    }
    zs[col][bl0]     = a0;
    zs[col][bl0 + 8] = a1;
    __syncthreads();

    if (tid < 128) {
        const int uu = tid & 7;
        const int bl = tid >> 3;            // 0..15
        float iv = zs[uu][bl];
        float jv = zs[8 + uu][bl];
        float fv = zs[16 + uu][bl];
        float ov = zs[24 + uu][bl];
        const int b = b0 + bl;
        const int idx = b * Uc + (u0 + uu);
        const bool m = (t < lengths[b]);
        float cold = c[idx];
        float cn = cold * sigm(fv + 1.0f) + sigm(iv) * tanhf(jv);
        float hn = tanhf(cn) * sigm(ov);
        if (m) { c[idx] = cn; h_next[idx] = hn; }
        else   { h_next[idx] = h_prev[idx]; }
    }
}

// ---------------- output head ----------------
__global__ void final_kernel(const float* __restrict__ hs,
                             const float* __restrict__ hb,
                             const float* __restrict__ ha,
                             const float* __restrict__ fW,  // (768, 82)
                             const float* __restrict__ fb,  // (82)
                             float* __restrict__ out) {     // (B, 82)
    const int b = blockIdx.x;
    const int tid = threadIdx.x; // 128
    __shared__ float hcat[3 * Uc];
    for (int idx = tid; idx < 3 * Uc; idx += 128) {
        float v;
        if (idx < Uc)            v = hs[b * Uc + idx];
        else if (idx < 2 * Uc)   v = hb[b * Uc + idx - Uc];
        else                     v = ha[b * Uc + idx - 2 * Uc];
        hcat[idx] = v;
    }
    __syncthreads();
    if (tid < NOUTc) {
        float acc = fb[tid];
#pragma unroll 2
        for (int k = 0; k < 3 * Uc; k++) acc = fmaf(hcat[k], fW[k * NOUTc + tid], acc);
        out[b * NOUTc + tid] = acc;
    }
}

// ---------------- host driver ----------------
static void run_lstm(const float* x_base, const int* gather_ids, const float* gather_tab,
                     int mode, int Din, int T,
                     const float* W0, const float* b0,
                     const float* W1, const float* b1,
                     const int* lengths,
                     float* c0, float* h0a, float* h0b,
                     float* c1, float* h1a, float* h1b) {
    dim3 grid(32, 8);
    float* h0buf[2] = { h0a, h0b };
    float* h1buf[2] = { h1a, h1b };
    for (int t = 0; t < T; t++) {
        const float* h0p = h0buf[t & 1];
        float*       h0n = h0buf[(t + 1) & 1];
        lstm_step_kernel<<<grid, 256>>>(x_base, gather_ids, gather_tab, mode, Din, T, t,
                                        W0, b0, lengths, h0p, c0, h0n);
        const float* h1p = h1buf[t & 1];
        float*       h1n = h1buf[(t + 1) & 1];
        lstm_step_kernel<<<grid, 256>>>(h0n, nullptr, nullptr, 1, Uc, T, t,
                                        W1, b1, lengths, h1p, c1, h1n);
    }
}

extern "C" void kernel_launch(void* const* d_in, const int* in_sizes, int n_in,
                              void* d_out, int out_size) {
    const int*   buff_word_id   = (const int*)d_in[0];
    const int*   buff_pos_id    = (const int*)d_in[1];
    const int*   comp_word_id   = (const int*)d_in[2];
    const int*   comp_pos_id    = (const int*)d_in[3];
    const int*   comp_action_id = (const int*)d_in[4];
    const int*   comp_action_len= (const int*)d_in[5];
    const int*   history_action_id = (const int*)d_in[6];
    const int*   stack_length   = (const int*)d_in[7];
    const int*   buff_length    = (const int*)d_in[8];
    const int*   history_action_length = (const int*)d_in[9];
    const float* p_emb      = (const float*)d_in[10];
    const float* comp_a_emb = (const float*)d_in[11];
    const float* hist_a_emb = (const float*)d_in[12];
    const float* w_emb      = (const float*)d_in[13];
    const float* emb_W      = (const float*)d_in[14];
    const float* emb_b      = (const float*)d_in[15];
    const float* rec_W      = (const float*)d_in[16];
    const float* rec_b      = (const float*)d_in[17];
    const float* sW0 = (const float*)d_in[18];
    const float* sb0 = (const float*)d_in[19];
    const float* sW1 = (const float*)d_in[20];
    const float* sb1 = (const float*)d_in[21];
    const float* bW0 = (const float*)d_in[22];
    const float* bb0 = (const float*)d_in[23];
    const float* bW1 = (const float*)d_in[24];
    const float* bb1 = (const float*)d_in[25];
    const float* aW0 = (const float*)d_in[26];
    const float* ab0 = (const float*)d_in[27];
    const float* aW1 = (const float*)d_in[28];
    const float* ab1 = (const float*)d_in[29];
    const float* fW  = (const float*)d_in[30];
    const float* fb  = (const float*)d_in[31];
    float* out = (float*)d_out;

    float *buff_emb_p, *comp_emb_p, *stack_emb_p;
    float *c0_p, *c1_p, *h0_p, *h1_p;
    cudaGetSymbolAddress((void**)&buff_emb_p,  g_buff_emb);
    cudaGetSymbolAddress((void**)&comp_emb_p,  g_comp_emb);
    cudaGetSymbolAddress((void**)&stack_emb_p, g_stack_emb);
    cudaGetSymbolAddress((void**)&c0_p, g_c0);
    cudaGetSymbolAddress((void**)&c1_p, g_c1);
    cudaGetSymbolAddress((void**)&h0_p, g_h0);
    cudaGetSymbolAddress((void**)&h1_p, g_h1);

    const size_t SB = (size_t)Bc * Uc;   // floats per state buffer

    // zero initial states (graph-capturable memsets)
    cudaMemsetAsync(c0_p, 0, 3 * SB * sizeof(float));
    cudaMemsetAsync(c1_p, 0, 3 * SB * sizeof(float));
    cudaMemsetAsync(h0_p, 0, 3 * 2 * SB * sizeof(float));
    cudaMemsetAsync(h1_p, 0, 3 * 2 * SB * sizeof(float));

    // embeddings
    const int nbuff = Bc * BUFFc;
    embed_kernel<<<(nbuff + 7) / 8, 128>>>(buff_word_id, buff_pos_id, w_emb, p_emb,
                                           emb_W, emb_b, buff_emb_p, nbuff);
    const int ncomp = Bc * STKc * 16;
    embed_kernel<<<(ncomp + 7) / 8, 128>>>(comp_word_id, comp_pos_id, w_emb, p_emb,
                                           emb_W, emb_b, comp_emb_p, ncomp);

    // recursive compose -> stack_emb
    compose_kernel<<<Bc * STKc, 128>>>(comp_word_id, comp_emb_p, comp_action_id,
                                       comp_action_len, comp_a_emb, rec_W, rec_b,
                                       stack_emb_p);

    // three 2-layer LSTMs (sequential on one stream; overlap is a later round)
    // lstm 0: stack  (T=48, Din=128)
    run_lstm(stack_emb_p, nullptr, nullptr, 0, FCc, STKc,
             sW0, sb0, sW1, sb1, stack_length,
             c0_p + 0 * SB, h0_p + (0 * 2 + 0) * SB, h0_p + (0 * 2 + 1) * SB,
             c1_p + 0 * SB, h1_p + (0 * 2 + 0) * SB, h1_p + (0 * 2 + 1) * SB);
    // lstm 1: buffer (T=64, Din=128)
    run_lstm(buff_emb_p, nullptr, nullptr, 0, FCc, BUFFc,
             bW0, bb0, bW1, bb1, buff_length,
             c0_p + 1 * SB, h0_p + (1 * 2 + 0) * SB, h0_p + (1 * 2 + 1) * SB,
             c1_p + 1 * SB, h1_p + (1 * 2 + 0) * SB, h1_p + (1 * 2 + 1) * SB);
    // lstm 2: action (T=96, Din=50, gathered from hist_a_emb)
    run_lstm(nullptr, history_action_id, hist_a_emb, 2, HADc, HISTc,
             aW0, ab0, aW1, ab1, history_action_length,
             c0_p + 2 * SB, h0_p + (2 * 2 + 0) * SB, h0_p + (2 * 2 + 1) * SB,
             c1_p + 2 * SB, h1_p + (2 * 2 + 0) * SB, h1_p + (2 * 2 + 1) * SB);

    // output head: final h1 lives in buffer 0 for T = 48 / 64 / 96 (all even)
    final_kernel<<<Bc, 128>>>(h1_p + (0 * 2 + 0) * SB,
                              h1_p + (1 * 2 + 0) * SB,
                              h1_p + (2 * 2 + 0) * SB,
                              fW, fb, out);
}

// round 3
// speedup vs baseline: 1.5112x; 1.4630x over previous
#include <cuda_runtime.h>
#include <math.h>

// ---------------- problem constants ----------------
#define Bc    128
#define BUFFc 64
#define STKc  48
#define HISTc 96
#define FCc   128
#define Uc    256
#define NOUTc 82
#define WDIMc 300
#define POSDc 50
#define EDINc 350     // WDIM + POSD
#define CADc  50
#define RDINc 306     // FC + CAD + FC
#define XS_PAD 36     // padded row stride for transposed x tile (16B aligned)

// ---------------- device scratch (no allocations allowed) ----------------
__device__ float g_buff_emb[Bc * BUFFc * FCc];
__device__ float g_comp_emb[Bc * STKc * 16 * FCc];
__device__ float g_stack_emb[Bc * STKc * FCc];

__device__ float g_z [6][Bc * 1024];
__device__ float g_c0[3][Bc * Uc];
__device__ float g_c1[3][Bc * Uc];
__device__ float g_h0[3][Bc * Uc];
__device__ float g_h1[3][Bc * Uc];

__device__ __forceinline__ float sigm(float x) { return 1.0f / (1.0f + expf(-x)); }

// ---------------- job descriptors (passed by value) ----------------
struct GJob {
    const float* x;     // strided source (mode 0/1)
    const int*   ids;   // gather ids (mode 2)
    const float* tab;   // gather table (mode 2)
    const float* W;     // (Dtot, 1024) row-major
    const float* h;     // (128, 256) recurrent input
    float*       z;     // (128, 1024) output
    int mode;           // 0: x[(b*T+t)*Din+k], 1: x[b*Din+k], 2: tab[ids[b*T+t]*Din+k]
    int Din, T, t, Dtot;
};
struct GJobs { GJob j[6]; };

struct UJob {
    const float* z;     // (128,1024)
    const float* bias;  // (1024)
    float*       c;     // (128,256) in-place
    float*       h;     // (128,256) in-place (write only when masked-in)
    const int*   len;
    int t;
};
struct UJobs { UJob j[6]; };

// ---------------- fused multi-job LSTM GEMM ----------------
// z = [x_t, h_prev] @ W   for each job. Block tile: 32 batches x 64 cols.
// 128 threads, thread tile 4x4, k-tiles of 32.
// grid = (64, njobs), block = 128.
__global__ void lstm_gemm_kernel(GJobs jobs) {
    const GJob J = jobs.j[blockIdx.y];
    const int bm = blockIdx.x & 3;    // batch tile (32 each)
    const int bn = blockIdx.x >> 2;   // col tile  (64 each)
    const int tid = threadIdx.x;

    __shared__ float xs[32][XS_PAD];  // [k][m]
    __shared__ float ws[32][64];      // [k][n]

    const int mi = tid & 7;           // 0..7  -> m0 = mi*4
    const int ni = tid >> 3;          // 0..15 -> n0 = ni*4
    const int m0 = mi * 4;
    const int n0t = ni * 4;
    const int b0 = bm * 32;
    const int n0 = bn * 64;

    float acc[4][4];
#pragma unroll
    for (int a = 0; a < 4; a++)
#pragma unroll
        for (int b = 0; b < 4; b++) acc[a][b] = 0.0f;

    const int nk = (J.Dtot + 31) >> 5;

    // staging thread mappings
    const int skk = tid & 31;         // k within tile (coalesced global x reads)
    const int smb = tid >> 5;         // 0..3 -> warp covers 8 m rows
    const int wc4 = tid & 15;         // float4 col within W tile row
    const int wk0 = tid >> 4;         // 0..7

    for (int kt = 0; kt < nk; kt++) {
        const int k0 = kt << 5;
        __syncthreads();

        // stage X (transposed): xs[k][m]
#pragma unroll
        for (int mm = 0; mm < 8; mm++) {
            const int m = smb * 8 + mm;
            const int k = k0 + skk;
            const int b = b0 + m;
            float v = 0.0f;
            if (k < J.Dtot) {
                if (k < J.Din) {
                    if (J.mode == 0)      v = J.x[(b * J.T + J.t) * J.Din + k];
                    else if (J.mode == 1) v = J.x[b * J.Din + k];
                    else                  v = J.tab[J.ids[b * J.T + J.t] * J.Din + k];
                } else {
                    v = J.h[b * Uc + (k - J.Din)];
                }
            }
            xs[skk][m] = v;
        }

        // stage W: ws[k][n] (float4 loads)
#pragma unroll
        for (int q = 0; q < 4; q++) {
            const int kk = wk0 + 8 * q;
            const int k = k0 + kk;
            float4 wv = make_float4(0.f, 0.f, 0.f, 0.f);
            if (k < J.Dtot)
                wv = *reinterpret_cast<const float4*>(J.W + (size_t)k * 1024 + n0 + wc4 * 4);
            *reinterpret_cast<float4*>(&ws[kk][wc4 * 4]) = wv;
        }
        __syncthreads();

        // compute: 2 LDS.128 + 16 FFMA per k
#pragma unroll 8
        for (int kk = 0; kk < 32; kk++) {
            const float4 xv = *reinterpret_cast<const float4*>(&xs[kk][m0]);
            const float4 wv = *reinterpret_cast<const float4*>(&ws[kk][n0t]);
            acc[0][0] = fmaf(xv.x, wv.x, acc[0][0]);
            acc[0][1] = fmaf(xv.x, wv.y, acc[0][1]);
            acc[0][2] = fmaf(xv.x, wv.z, acc[0][2]);
            acc[0][3] = fmaf(xv.x, wv.w, acc[0][3]);
            acc[1][0] = fmaf(xv.y, wv.x, acc[1][0]);
            acc[1][1] = fmaf(xv.y, wv.y, acc[1][1]);
            acc[1][2] = fmaf(xv.y, wv.z, acc[1][2]);
            acc[1][3] = fmaf(xv.y, wv.w, acc[1][3]);
            acc[2][0] = fmaf(xv.z, wv.x, acc[2][0]);
            acc[2][1] = fmaf(xv.z, wv.y, acc[2][1]);
            acc[2][2] = fmaf(xv.z, wv.z, acc[2][2]);
            acc[2][3] = fmaf(xv.z, wv.w, acc[2][3]);
            acc[3][0] = fmaf(xv.w, wv.x, acc[3][0]);
            acc[3][1] = fmaf(xv.w, wv.y, acc[3][1]);
            acc[3][2] = fmaf(xv.w, wv.z, acc[3][2]);
            acc[3][3] = fmaf(xv.w, wv.w, acc[3][3]);
        }
    }

    // epilogue: write z tile
#pragma unroll
    for (int a = 0; a < 4; a++) {
        const int b = b0 + m0 + a;
        float4 v = make_float4(acc[a][0], acc[a][1], acc[a][2], acc[a][3]);
        *reinterpret_cast<float4*>(J.z + (size_t)b * 1024 + n0 + n0t) = v;
    }
}

// ---------------- fused multi-job gates / cell update ----------------
// grid = (128, njobs), block = 256. u = tid.
__global__ void lstm_gates_kernel(UJobs jobs) {
    const UJob J = jobs.j[blockIdx.y];
    const int b = blockIdx.x;
    const int u = threadIdx.x;
    if (J.t >= J.len[b]) return;   // masked out: keep c, h

    const float* zr = J.z + (size_t)b * 1024;
    const float iv = zr[u]           + J.bias[u];
    const float jv = zr[256 + u]     + J.bias[256 + u];
    const float fv = zr[512 + u]     + J.bias[512 + u];
    const float ov = zr[768 + u]     + J.bias[768 + u];

    const int idx = b * Uc + u;
    const float cold = J.c[idx];
    const float cn = cold * sigm(fv + 1.0f) + sigm(iv) * tanhf(jv);
    const float hn = tanhf(cn) * sigm(ov);
    J.c[idx] = cn;
    J.h[idx] = hn;
}

// ---------------- embedding: relu([w_emb[id], p_emb[pid]] @ emb_W + b) ----------------
__global__ void embed_kernel(const int* __restrict__ word_ids,
                             const int* __restrict__ pos_ids,
                             const float* __restrict__ w_emb,
                             const float* __restrict__ p_emb,
                             const float* __restrict__ W,
                             const float* __restrict__ bias,
                             float* __restrict__ out,
                             int nrows) {
    __shared__ float xs[8][EDINc];
    __shared__ int wid_s[8], pid_s[8];
    const int r0 = blockIdx.x * 8;
    const int tid = threadIdx.x;

    if (tid < 8) {
        int row = r0 + tid;
        wid_s[tid] = (row < nrows) ? word_ids[row] : 0;
        pid_s[tid] = (row < nrows) ? pos_ids[row] : 0;
    }
    __syncthreads();

    for (int idx = tid; idx < 8 * EDINc; idx += 128) {
        int r = idx / EDINc, k = idx - r * EDINc;
        float v;
        if (k < WDIMc) v = w_emb[wid_s[r] * WDIMc + k];
        else           v = p_emb[pid_s[r] * POSDc + (k - WDIMc)];
        xs[r][k] = v;
    }
    __syncthreads();

    float acc[8];
    const float bj = bias[tid];
#pragma unroll
    for (int r = 0; r < 8; r++) acc[r] = bj;

#pragma unroll 2
    for (int k = 0; k < EDINc; k++) {
        float w = W[k * FCc + tid];
#pragma unroll
        for (int r = 0; r < 8; r++) acc[r] = fmaf(xs[r][k], w, acc[r]);
    }
#pragma unroll
    for (int r = 0; r < 8; r++) {
        int row = r0 + r;
        if (row < nrows) out[row * FCc + tid] = fmaxf(acc[r], 0.0f);
    }
}

// ---------------- compose: recursive tree composition per (b, stk) ----------------
__global__ void compose_kernel(const int* __restrict__ comp_word_id,
                               const float* __restrict__ comp_emb,
                               const int* __restrict__ comp_action_id,
                               const int* __restrict__ comp_action_len,
                               const float* __restrict__ a_emb,
                               const float* __restrict__ rec_W,
                               const float* __restrict__ rec_b,
                               float* __restrict__ stack_emb) {
    const int seq = blockIdx.x;
    const int tid = threadIdx.x;
    __shared__ float vals[8][FCc];
    __shared__ float xbuf[RDINc];
    __shared__ int hid[8], did[8];

    if (tid < 8) {
        hid[tid] = comp_word_id[seq * 16 + 2 * tid];
        did[tid] = comp_word_id[seq * 16 + 2 * tid + 1];
    }
    __syncthreads();

    const float bj = rec_b[tid];
    for (int n = 0; n < 8; n++) {
        int ih = -1, idd = -1;
        for (int m = 0; m < n; m++) {
            if (hid[m] == hid[n]) ih = m;
            if (hid[m] == did[n]) idd = m;
        }
        float he = (ih  >= 0) ? vals[ih][tid]  : comp_emb[(seq * 16 + 2 * n) * FCc + tid];
        float de = (idd >= 0) ? vals[idd][tid] : comp_emb[(seq * 16 + 2 * n + 1) * FCc + tid];
        xbuf[tid] = he;
        xbuf[FCc + CADc + tid] = de;
        if (tid < CADc) xbuf[FCc + tid] = a_emb[comp_action_id[seq * 8 + n] * CADc + tid];
        __syncthreads();

        float acc = bj;
#pragma unroll 2
        for (int k = 0; k < RDINc; k++) acc = fmaf(xbuf[k], rec_W[k * FCc + tid], acc);
        vals[n][tid] = tanhf(acc);
        __syncthreads();
    }

    int al = comp_action_len[seq];
    float outv = (al == 0) ? comp_emb[(seq * 16) * FCc + tid] : vals[al - 1][tid];
    stack_emb[seq * FCc + tid] = outv;
}

// ---------------- output head ----------------
__global__ void final_kernel(const float* __restrict__ hs,
                             const float* __restrict__ hb,
                             const float* __restrict__ ha,
                             const float* __restrict__ fW,
                             const float* __restrict__ fb,
                             float* __restrict__ out) {
    const int b = blockIdx.x;
    const int tid = threadIdx.x;
    __shared__ float hcat[3 * Uc];
    for (int idx = tid; idx < 3 * Uc; idx += 128) {
        float v;
        if (idx < Uc)            v = hs[b * Uc + idx];
        else if (idx < 2 * Uc)   v = hb[b * Uc + idx - Uc];
        else                     v = ha[b * Uc + idx - 2 * Uc];
        hcat[idx] = v;
    }
    __syncthreads();
    if (tid < NOUTc) {
        float acc = fb[tid];
#pragma unroll 2
        for (int k = 0; k < 3 * Uc; k++) acc = fmaf(hcat[k], fW[k * NOUTc + tid], acc);
        out[b * NOUTc + tid] = acc;
    }
}

// ---------------- host driver ----------------
extern "C" void kernel_launch(void* const* d_in, const int* in_sizes, int n_in,
                              void* d_out, int out_size) {
    const int*   buff_word_id   = (const int*)d_in[0];
    const int*   buff_pos_id    = (const int*)d_in[1];
    const int*   comp_word_id   = (const int*)d_in[2];
    const int*   comp_pos_id    = (const int*)d_in[3];
    const int*   comp_action_id = (const int*)d_in[4];
    const int*   comp_action_len= (const int*)d_in[5];
    const int*   history_action_id = (const int*)d_in[6];
    const int*   stack_length   = (const int*)d_in[7];
    const int*   buff_length    = (const int*)d_in[8];
    const int*   history_action_length = (const int*)d_in[9];
    const float* p_emb      = (const float*)d_in[10];
    const float* comp_a_emb = (const float*)d_in[11];
    const float* hist_a_emb = (const float*)d_in[12];
    const float* w_emb      = (const float*)d_in[13];
    const float* emb_W      = (const float*)d_in[14];
    const float* emb_b      = (const float*)d_in[15];
    const float* rec_W      = (const float*)d_in[16];
    const float* rec_b      = (const float*)d_in[17];
    const float* W0s[3] = { (const float*)d_in[18], (const float*)d_in[22], (const float*)d_in[26] };
    const float* b0s[3] = { (const float*)d_in[19], (const float*)d_in[23], (const float*)d_in[27] };
    const float* W1s[3] = { (const float*)d_in[20], (const float*)d_in[24], (const float*)d_in[28] };
    const float* b1s[3] = { (const float*)d_in[21], (const float*)d_in[25], (const float*)d_in[29] };
    const float* fW  = (const float*)d_in[30];
    const float* fb  = (const float*)d_in[31];
    float* out = (float*)d_out;

    float *buff_emb_p, *comp_emb_p, *stack_emb_p;
    float *z_p, *c0_p, *c1_p, *h0_p, *h1_p;
    cudaGetSymbolAddress((void**)&buff_emb_p,  g_buff_emb);
    cudaGetSymbolAddress((void**)&comp_emb_p,  g_comp_emb);
    cudaGetSymbolAddress((void**)&stack_emb_p, g_stack_emb);
    cudaGetSymbolAddress((void**)&z_p,  g_z);
    cudaGetSymbolAddress((void**)&c0_p, g_c0);
    cudaGetSymbolAddress((void**)&c1_p, g_c1);
    cudaGetSymbolAddress((void**)&h0_p, g_h0);
    cudaGetSymbolAddress((void**)&h1_p, g_h1);

    const size_t SB = (size_t)Bc * Uc;
    const size_t ZB = (size_t)Bc * 1024;

    // zero initial states
    cudaMemsetAsync(c0_p, 0, 3 * SB * sizeof(float));
    cudaMemsetAsync(c1_p, 0, 3 * SB * sizeof(float));
    cudaMemsetAsync(h0_p, 0, 3 * SB * sizeof(float));
    cudaMemsetAsync(h1_p, 0, 3 * SB * sizeof(float));

    // embeddings
    const int nbuff = Bc * BUFFc;
    embed_kernel<<<(nbuff + 7) / 8, 128>>>(buff_word_id, buff_pos_id, w_emb, p_emb,
                                           emb_W, emb_b, buff_emb_p, nbuff);
    const int ncomp = Bc * STKc * 16;
    embed_kernel<<<(ncomp + 7) / 8, 128>>>(comp_word_id, comp_pos_id, w_emb, p_emb,
                                           emb_W, emb_b, comp_emb_p, ncomp);

    // recursive compose -> stack_emb
    compose_kernel<<<Bc * STKc, 128>>>(comp_word_id, comp_emb_p, comp_action_id,
                                       comp_action_len, comp_a_emb, rec_W, rec_b,
                                       stack_emb_p);

    // --- pipelined fused LSTM loop: layer0 at step i, layer1 at step i-1 ---
    const float* Xs[3]   = { stack_emb_p, buff_emb_p, nullptr };
    const int*   IDs[3]  = { nullptr, nullptr, history_action_id };
    const float* TABs[3] = { nullptr, nullptr, hist_a_emb };
    const int    MODE0[3]= { 0, 0, 2 };
    const int    DIN0[3] = { FCc, FCc, 50 };
    const int    DTOT0[3]= { FCc + Uc, FCc + Uc, 50 + Uc };
    const int    Ts[3]   = { STKc, BUFFc, HISTc };
    const int*   LEN[3]  = { stack_length, buff_length, history_action_length };

    for (int i = 0; i <= HISTc; i++) {
        GJobs gj;
        UJobs uj;
        int n = 0;
        for (int L = 0; L < 3; L++) {
            float* h0L = h0_p + L * SB;
            float* h1L = h1_p + L * SB;
            float* c0L = c0_p + L * SB;
            float* c1L = c1_p + L * SB;
            if (i < Ts[L]) {                       // layer0, step t = i
                float* z = z_p + (2 * L) * ZB;
                gj.j[n] = GJob{ Xs[L], IDs[L], TABs[L], W0s[L], h0L, z,
                                MODE0[L], DIN0[L], Ts[L], i, DTOT0[L] };
                uj.j[n] = UJob{ z, b0s[L], c0L, h0L, LEN[L], i };
                n++;
            }
            if (i >= 1 && i <= Ts[L]) {            // layer1, step t = i-1
                float* z = z_p + (2 * L + 1) * ZB;
                gj.j[n] = GJob{ h0L, nullptr, nullptr, W1s[L], h1L, z,
                                1, Uc, Ts[L], i - 1, Uc + Uc };
                uj.j[n] = UJob{ z, b1s[L], c1L, h1L, LEN[L], i - 1 };
                n++;
            }
        }
        if (n > 0) {
            lstm_gemm_kernel<<<dim3(64, n), 128>>>(gj);
            lstm_gates_kernel<<<dim3(Bc, n), 256>>>(uj);
        }
    }

    // output head
    final_kernel<<<Bc, 128>>>(h1_p + 0 * SB, h1_p + 1 * SB, h1_p + 2 * SB,
                              fW, fb, out);
}

// round 4
// speedup vs baseline: 4.3648x; 2.8884x over previous
#include <cuda_runtime.h>
#include <math.h>

// ---------------- problem constants ----------------
#define Bc    128
#define BUFFc 64
#define STKc  48
#define HISTc 96
#define FCc   128
#define Uc    256
#define NOUTc 82
#define WDIMc 300
#define POSDc 50
#define EDINc 350     // WDIM + POSD
#define CADc  50
#define RDINc 306     // FC + CAD + FC

// ---------------- device scratch (no allocations allowed) ----------------
__device__ float g_buff_emb[Bc * BUFFc * FCc];
__device__ float g_comp_emb[Bc * STKc * 16 * FCc];
__device__ float g_stack_emb[Bc * STKc * FCc];

__device__ float g_zx0[Bc * STKc  * 1024];   // 25 MB  precomputed x-projections
__device__ float g_zx1[Bc * BUFFc * 1024];   // 33 MB
__device__ float g_zx2[Bc * HISTc * 1024];   // 50 MB
__device__ float g_zp [9][Bc * 1024];        // per-iteration partials

__device__ float g_c0[3][Bc * Uc];
__device__ float g_c1[3][Bc * Uc];
__device__ float g_h0[3][Bc * Uc];
__device__ float g_h1[3][Bc * Uc];

__device__ __forceinline__ float sigm(float x) { return 1.0f / (1.0f + expf(-x)); }

// ---------------- hot sequential GEMM: zp = src(128x256) @ W256(256x1024) ----------------
// Fixed K=256. Block: 256 threads, tile 32m x 128n, thread tile 4x4,
// double-buffered SMEM, 8 k-tiles of 32. grid = (32, nunits).
struct KUnit { const float* src; const float* W; float* zp; };
struct KUnits { KUnit u[9]; };

__global__ void __launch_bounds__(256, 2) hgemm_kernel(KUnits units) {
    const KUnit U = units.u[blockIdx.y];
    const int tid = threadIdx.x;
    const int bm = blockIdx.x & 3;     // 4 m-tiles
    const int bn = blockIdx.x >> 2;    // 8 n-tiles
    const int b0 = bm * 32;
    const int n0 = bn * 128;

    __shared__ float xs[2][32][33];                  // [buf][m][k] (scalar access)
    __shared__ __align__(16) float ws[2][32][128];   // [buf][k][n]

    const int mi = tid & 7,  ni = tid >> 3;          // thread tile coords
    const int m0 = mi * 4,   n0t = ni * 4;

    const int xm = tid >> 3;            // 0..31 : m row staged by this thread
    const int xk = (tid & 7) * 4;       // k float4 start
    const int wc = (tid & 31) * 4;      // n start for W staging
    const int wk = tid >> 5;            // 0..7 base k row

    float acc[4][4];
#pragma unroll
    for (int a = 0; a < 4; a++)
#pragma unroll
        for (int b = 0; b < 4; b++) acc[a][b] = 0.0f;

    const float* srow = U.src + (b0 + xm) * Uc;   // K = 256 row

    // ---- prologue: stage tile 0 ----
    {
        float4 xv = *(const float4*)(srow + xk);
        xs[0][xm][xk + 0] = xv.x; xs[0][xm][xk + 1] = xv.y;
        xs[0][xm][xk + 2] = xv.z; xs[0][xm][xk + 3] = xv.w;
#pragma unroll
        for (int q = 0; q < 4; q++) {
            const int kk = wk + 8 * q;
            *(float4*)&ws[0][kk][wc] =
                *(const float4*)(U.W + (size_t)kk * 1024 + n0 + wc);
        }
    }
    __syncthreads();

    int buf = 0;
#pragma unroll 1
    for (int kt = 0; kt < 8; kt++) {
        float4 xv;
        float4 wv0, wv1, wv2, wv3;
        if (kt < 7) {
            const int k0 = (kt + 1) * 32;
            xv  = *(const float4*)(srow + k0 + xk);
            wv0 = *(const float4*)(U.W + (size_t)(k0 + wk +  0) * 1024 + n0 + wc);
            wv1 = *(const float4*)(U.W + (size_t)(k0 + wk +  8) * 1024 + n0 + wc);
            wv2 = *(const float4*)(U.W + (size_t)(k0 + wk + 16) * 1024 + n0 + wc);
            wv3 = *(const float4*)(U.W + (size_t)(k0 + wk + 24) * 1024 + n0 + wc);
        }

        const float (*xsb)[33]  = xs[buf];
        const float (*wsb)[128] = ws[buf];
#pragma unroll
        for (int kk = 0; kk < 32; kk++) {
            const float x0 = xsb[m0 + 0][kk];
            const float x1 = xsb[m0 + 1][kk];
            const float x2 = xsb[m0 + 2][kk];
            const float x3 = xsb[m0 + 3][kk];
            const float4 w = *(const float4*)&wsb[kk][n0t];
            acc[0][0] = fmaf(x0, w.x, acc[0][0]);
            acc[0][1] = fmaf(x0, w.y, acc[0][1]);
            acc[0][2] = fmaf(x0, w.z, acc[0][2]);
            acc[0][3] = fmaf(x0, w.w, acc[0][3]);
            acc[1][0] = fmaf(x1, w.x, acc[1][0]);
            acc[1][1] = fmaf(x1, w.y, acc[1][1]);
            acc[1][2] = fmaf(x1, w.z, acc[1][2]);
            acc[1][3] = fmaf(x1, w.w, acc[1][3]);
            acc[2][0] = fmaf(x2, w.x, acc[2][0]);
            acc[2][1] = fmaf(x2, w.y, acc[2][1]);
            acc[2][2] = fmaf(x2, w.z, acc[2][2]);
            acc[2][3] = fmaf(x2, w.w, acc[2][3]);
            acc[3][0] = fmaf(x3, w.x, acc[3][0]);
            acc[3][1] = fmaf(x3, w.y, acc[3][1]);
            acc[3][2] = fmaf(x3, w.z, acc[3][2]);
            acc[3][3] = fmaf(x3, w.w, acc[3][3]);
        }

        if (kt < 7) {
            const int nb = buf ^ 1;
            xs[nb][xm][xk + 0] = xv.x; xs[nb][xm][xk + 1] = xv.y;
            xs[nb][xm][xk + 2] = xv.z; xs[nb][xm][xk + 3] = xv.w;
            *(float4*)&ws[nb][wk +  0][wc] = wv0;
            *(float4*)&ws[nb][wk +  8][wc] = wv1;
            *(float4*)&ws[nb][wk + 16][wc] = wv2;
            *(float4*)&ws[nb][wk + 24][wc] = wv3;
            __syncthreads();
            buf = nb;
        }
    }

#pragma unroll
    for (int a = 0; a < 4; a++) {
        *(float4*)(U.zp + (size_t)(b0 + m0 + a) * 1024 + n0 + n0t) =
            make_float4(acc[a][0], acc[a][1], acc[a][2], acc[a][3]);
    }
}

// ---------------- gates / cell update (sums partials) ----------------
struct UJob {
    const float* zx;    // precomputed x projection (layer0) or null
    const float* p0;    // partial 0
    const float* p1;    // partial 1 (layer1) or null
    const float* bias;
    float* c;
    float* h;
    const int* len;
    int T, t;
};
struct UJobs { UJob j[6]; };

__global__ void lstm_gates_kernel(UJobs jobs) {
    const UJob J = jobs.j[blockIdx.y];
    const int b = blockIdx.x;
    const int u = threadIdx.x;
    if (J.t >= J.len[b]) return;   // masked: keep c and h

    float g[4];
#pragma unroll
    for (int gg = 0; gg < 4; gg++) {
        const int col = gg * 256 + u;
        float v = J.p0[(size_t)b * 1024 + col] + J.bias[col];
        if (J.p1) v += J.p1[(size_t)b * 1024 + col];
        if (J.zx) v += J.zx[((size_t)b * J.T + J.t) * 1024 + col];
        g[gg] = v;
    }
    const int idx = b * Uc + u;
    const float cn = J.c[idx] * sigm(g[2] + 1.0f) + sigm(g[0]) * tanhf(g[1]);
    const float hn = tanhf(cn) * sigm(g[3]);
    J.c[idx] = cn;
    J.h[idx] = hn;
}

// ---------------- x-projection precompute: zx = X(rows x Din) @ W(Din x 1024) ----------------
struct XJob { const float* x; const int* ids; const float* tab;
              const float* W; float* zx; int rows, Din; };
struct XJobs { XJob j[3]; };

__global__ void xproj_kernel(XJobs jobs) {
    const XJob J = jobs.j[blockIdx.y];
    const int bm = blockIdx.x % 384;
    const int bn = blockIdx.x / 384;
    const int r0 = bm * 32;
    if (r0 >= J.rows) return;
    const int n0 = bn * 128;

    __shared__ float xs[32][33];
    __shared__ __align__(16) float ws[32][128];
    const int tid = threadIdx.x;
    const int mi = tid & 7, ni = tid >> 3;
    const int m0 = mi * 4, n0t = ni * 4;
    const int xm = tid >> 3, xk = (tid & 7) * 4;
    const int wc = (tid & 31) * 4, wk = tid >> 5;

    float acc[4][4];
#pragma unroll
    for (int a = 0; a < 4; a++)
#pragma unroll
        for (int b = 0; b < 4; b++) acc[a][b] = 0.0f;

    const int r = r0 + xm;
    const float* srow = J.ids ? (J.tab + (size_t)J.ids[r] * J.Din)
                              : (J.x + (size_t)r * J.Din);

    const int nk = (J.Din + 31) >> 5;
    for (int kt = 0; kt < nk; kt++) {
        const int k0 = kt * 32;
        __syncthreads();
#pragma unroll
        for (int j = 0; j < 4; j++) {
            const int k = k0 + xk + j;
            xs[xm][xk + j] = (k < J.Din) ? srow[k] : 0.0f;
        }
#pragma unroll
        for (int q = 0; q < 4; q++) {
            const int kk = wk + 8 * q, k = k0 + kk;
            float4 wv = make_float4(0.f, 0.f, 0.f, 0.f);
            if (k < J.Din)
                wv = *(const float4*)(J.W + (size_t)k * 1024 + n0 + wc);
            *(float4*)&ws[kk][wc] = wv;
        }
        __syncthreads();
#pragma unroll 8
        for (int kk = 0; kk < 32; kk++) {
            const float x0 = xs[m0 + 0][kk];
            const float x1 = xs[m0 + 1][kk];
            const float x2 = xs[m0 + 2][kk];
            const float x3 = xs[m0 + 3][kk];
            const float4 w = *(const float4*)&ws[kk][n0t];
            acc[0][0] = fmaf(x0, w.x, acc[0][0]);
            acc[0][1] = fmaf(x0, w.y, acc[0][1]);
            acc[0][2] = fmaf(x0, w.z, acc[0][2]);
            acc[0][3] = fmaf(x0, w.w, acc[0][3]);
            acc[1][0] = fmaf(x1, w.x, acc[1][0]);
            acc[1][1] = fmaf(x1, w.y, acc[1][1]);
            acc[1][2] = fmaf(x1, w.z, acc[1][2]);
            acc[1][3] = fmaf(x1, w.w, acc[1][3]);
            acc[2][0] = fmaf(x2, w.x, acc[2][0]);
            acc[2][1] = fmaf(x2, w.y, acc[2][1]);
            acc[2][2] = fmaf(x2, w.z, acc[2][2]);
            acc[2][3] = fmaf(x2, w.w, acc[2][3]);
            acc[3][0] = fmaf(x3, w.x, acc[3][0]);
            acc[3][1] = fmaf(x3, w.y, acc[3][1]);
            acc[3][2] = fmaf(x3, w.z, acc[3][2]);
            acc[3][3] = fmaf(x3, w.w, acc[3][3]);
        }
    }
#pragma unroll
    for (int a = 0; a < 4; a++) {
        *(float4*)(J.zx + (size_t)(r0 + m0 + a) * 1024 + n0 + n0t) =
            make_float4(acc[a][0], acc[a][1], acc[a][2], acc[a][3]);
    }
}

// ---------------- embedding: relu([w_emb[id], p_emb[pid]] @ emb_W + b) ----------------
__global__ void embed_kernel(const int* __restrict__ word_ids,
                             const int* __restrict__ pos_ids,
                             const float* __restrict__ w_emb,
                             const float* __restrict__ p_emb,
                             const float* __restrict__ W,
                             const float* __restrict__ bias,
                             float* __restrict__ out,
                             int nrows) {
    __shared__ float xs[8][EDINc];
    __shared__ int wid_s[8], pid_s[8];
    const int r0 = blockIdx.x * 8;
    const int tid = threadIdx.x;

    if (tid < 8) {
        int row = r0 + tid;
        wid_s[tid] = (row < nrows) ? word_ids[row] : 0;
        pid_s[tid] = (row < nrows) ? pos_ids[row] : 0;
    }
    __syncthreads();

    for (int idx = tid; idx < 8 * EDINc; idx += 128) {
        int r = idx / EDINc, k = idx - r * EDINc;
        float v;
        if (k < WDIMc) v = w_emb[wid_s[r] * WDIMc + k];
        else           v = p_emb[pid_s[r] * POSDc + (k - WDIMc)];
        xs[r][k] = v;
    }
    __syncthreads();

    float acc[8];
    const float bj = bias[tid];
#pragma unroll
    for (int r = 0; r < 8; r++) acc[r] = bj;

#pragma unroll 2
    for (int k = 0; k < EDINc; k++) {
        float w = W[k * FCc + tid];
#pragma unroll
        for (int r = 0; r < 8; r++) acc[r] = fmaf(xs[r][k], w, acc[r]);
    }
#pragma unroll
    for (int r = 0; r < 8; r++) {
        int row = r0 + r;
        if (row < nrows) out[row * FCc + tid] = fmaxf(acc[r], 0.0f);
    }
}

// ---------------- compose: recursive tree composition per (b, stk) ----------------
__global__ void compose_kernel(const int* __restrict__ comp_word_id,
                               const float* __restrict__ comp_emb,
                               const int* __restrict__ comp_action_id,
                               const int* __restrict__ comp_action_len,
                               const float* __restrict__ a_emb,
                               const float* __restrict__ rec_W,
                               const float* __restrict__ rec_b,
                               float* __restrict__ stack_emb) {
    const int seq = blockIdx.x;
    const int tid = threadIdx.x;
    __shared__ float vals[8][FCc];
    __shared__ float xbuf[RDINc];
    __shared__ int hid[8], did[8];

    if (tid < 8) {
        hid[tid] = comp_word_id[seq * 16 + 2 * tid];
        did[tid] = comp_word_id[seq * 16 + 2 * tid + 1];
    }
    __syncthreads();

    const float bj = rec_b[tid];
    for (int n = 0; n < 8; n++) {
        int ih = -1, idd = -1;
        for (int m = 0; m < n; m++) {
            if (hid[m] == hid[n]) ih = m;
            if (hid[m] == did[n]) idd = m;
        }
        float he = (ih  >= 0) ? vals[ih][tid]  : comp_emb[(seq * 16 + 2 * n) * FCc + tid];
        float de = (idd >= 0) ? vals[idd][tid] : comp_emb[(seq * 16 + 2 * n + 1) * FCc + tid];
        xbuf[tid] = he;
        xbuf[FCc + CADc + tid] = de;
        if (tid < CADc) xbuf[FCc + tid] = a_emb[comp_action_id[seq * 8 + n] * CADc + tid];
        __syncthreads();

        float acc = bj;
#pragma unroll 2
        for (int k = 0; k < RDINc; k++) acc = fmaf(xbuf[k], rec_W[k * FCc + tid], acc);
        vals[n][tid] = tanhf(acc);
        __syncthreads();
    }

    int al = comp_action_len[seq];
    float outv = (al == 0) ? comp_emb[(seq * 16) * FCc + tid] : vals[al - 1][tid];
    stack_emb[seq * FCc + tid] = outv;
}

// ---------------- output head ----------------
__global__ void final_kernel(const float* __restrict__ hs,
                             const float* __restrict__ hb,
                             const float* __restrict__ ha,
                             const float* __restrict__ fW,
                             const float* __restrict__ fb,
                             float* __restrict__ out) {
    const int b = blockIdx.x;
    const int tid = threadIdx.x;
    __shared__ float hcat[3 * Uc];
    for (int idx = tid; idx < 3 * Uc; idx += 128) {
        float v;
        if (idx < Uc)            v = hs[b * Uc + idx];
        else if (idx < 2 * Uc)   v = hb[b * Uc + idx - Uc];
        else                     v = ha[b * Uc + idx - 2 * Uc];
        hcat[idx] = v;
    }
    __syncthreads();
    if (tid < NOUTc) {
        float acc = fb[tid];
#pragma unroll 2
        for (int k = 0; k < 3 * Uc; k++) acc = fmaf(hcat[k], fW[k * NOUTc + tid], acc);
        out[b * NOUTc + tid] = acc;
    }
}

// ---------------- host driver ----------------
extern "C" void kernel_launch(void* const* d_in, const int* in_sizes, int n_in,
                              void* d_out, int out_size) {
    const int*   buff_word_id   = (const int*)d_in[0];
    const int*   buff_pos_id    = (const int*)d_in[1];
    const int*   comp_word_id   = (const int*)d_in[2];
    const int*   comp_pos_id    = (const int*)d_in[3];
    const int*   comp_action_id = (const int*)d_in[4];
    const int*   comp_action_len= (const int*)d_in[5];
    const int*   history_action_id = (const int*)d_in[6];
    const int*   stack_length   = (const int*)d_in[7];
    const int*   buff_length    = (const int*)d_in[8];
    const int*   history_action_length = (const int*)d_in[9];
    const float* p_emb      = (const float*)d_in[10];
    const float* comp_a_emb = (const float*)d_in[11];
    const float* hist_a_emb = (const float*)d_in[12];
    const float* w_emb      = (const float*)d_in[13];
    const float* emb_W      = (const float*)d_in[14];
    const float* emb_b      = (const float*)d_in[15];
    const float* rec_W      = (const float*)d_in[16];
    const float* rec_b      = (const float*)d_in[17];
    const float* W0s[3] = { (const float*)d_in[18], (const float*)d_in[22], (const float*)d_in[26] };
    const float* b0s[3] = { (const float*)d_in[19], (const float*)d_in[23], (const float*)d_in[27] };
    const float* W1s[3] = { (const float*)d_in[20], (const float*)d_in[24], (const float*)d_in[28] };
    const float* b1s[3] = { (const float*)d_in[21], (const float*)d_in[25], (const float*)d_in[29] };
    const float* fW  = (const float*)d_in[30];
    const float* fb  = (const float*)d_in[31];
    float* out = (float*)d_out;

    float *buff_emb_p, *comp_emb_p, *stack_emb_p;
    float *zx0_p, *zx1_p, *zx2_p, *zp_p;
    float *c0_p, *c1_p, *h0_p, *h1_p;
    cudaGetSymbolAddress((void**)&buff_emb_p,  g_buff_emb);
    cudaGetSymbolAddress((void**)&comp_emb_p,  g_comp_emb);
    cudaGetSymbolAddress((void**)&stack_emb_p, g_stack_emb);
    cudaGetSymbolAddress((void**)&zx0_p, g_zx0);
    cudaGetSymbolAddress((void**)&zx1_p, g_zx1);
    cudaGetSymbolAddress((void**)&zx2_p, g_zx2);
    cudaGetSymbolAddress((void**)&zp_p,  g_zp);
    cudaGetSymbolAddress((void**)&c0_p, g_c0);
    cudaGetSymbolAddress((void**)&c1_p, g_c1);
    cudaGetSymbolAddress((void**)&h0_p, g_h0);
    cudaGetSymbolAddress((void**)&h1_p, g_h1);

    const size_t SB = (size_t)Bc * Uc;
    const size_t ZPB = (size_t)Bc * 1024;

    cudaMemsetAsync(c0_p, 0, 3 * SB * sizeof(float));
    cudaMemsetAsync(c1_p, 0, 3 * SB * sizeof(float));
    cudaMemsetAsync(h0_p, 0, 3 * SB * sizeof(float));
    cudaMemsetAsync(h1_p, 0, 3 * SB * sizeof(float));

    // embeddings
    const int nbuff = Bc * BUFFc;
    embed_kernel<<<(nbuff + 7) / 8, 128>>>(buff_word_id, buff_pos_id, w_emb, p_emb,
                                           emb_W, emb_b, buff_emb_p, nbuff);
    const int ncomp = Bc * STKc * 16;
    embed_kernel<<<(ncomp + 7) / 8, 128>>>(comp_word_id, comp_pos_id, w_emb, p_emb,
                                           emb_W, emb_b, comp_emb_p, ncomp);

    // recursive compose -> stack_emb
    compose_kernel<<<Bc * STKc, 128>>>(comp_word_id, comp_emb_p, comp_action_id,
                                       comp_action_len, comp_a_emb, rec_W, rec_b,
                                       stack_emb_p);

    // precompute x-projections for layer0 of all three LSTMs
    {
        XJobs xj;
        xj.j[0] = XJob{ stack_emb_p, nullptr, nullptr, W0s[0], zx0_p, Bc * STKc,  FCc };
        xj.j[1] = XJob{ buff_emb_p,  nullptr, nullptr, W0s[1], zx1_p, Bc * BUFFc, FCc };
        xj.j[2] = XJob{ nullptr, history_action_id, hist_a_emb, W0s[2], zx2_p, Bc * HISTc, 50 };
        xproj_kernel<<<dim3(384 * 8, 3), 256>>>(xj);
    }

    // --- pipelined sequential loop: layer0 at step i, layer1 at step i-1 ---
    const float* ZXs[3] = { zx0_p, zx1_p, zx2_p };
    const int    DIN0[3]= { FCc, FCc, 50 };
    const int    Ts[3]  = { STKc, BUFFc, HISTc };
    const int*   LEN[3] = { stack_length, buff_length, history_action_length };

    for (int i = 0; i <= HISTc; i++) {
        KUnits ku;
        UJobs uj;
        int nu = 0, nj = 0;
        for (int L = 0; L < 3; L++) {
            float* h0L = h0_p + L * SB;
            float* h1L = h1_p + L * SB;
            float* c0L = c0_p + L * SB;
            float* c1L = c1_p + L * SB;
            float* zpL0 = zp_p + (size_t)(L * 3 + 0) * ZPB;
            float* zpLA = zp_p + (size_t)(L * 3 + 1) * ZPB;
            float* zpLB = zp_p + (size_t)(L * 3 + 2) * ZPB;
            if (i < Ts[L]) {                      // layer0 step t = i (h-part only)
                ku.u[nu++] = KUnit{ h0L, W0s[L] + (size_t)DIN0[L] * 1024, zpL0 };
                uj.j[nj++] = UJob{ ZXs[L], zpL0, nullptr, b0s[L],
                                   c0L, h0L, LEN[L], Ts[L], i };
            }
            if (i >= 1 && i <= Ts[L]) {           // layer1 step t = i-1 (two K-chunks)
                ku.u[nu++] = KUnit{ h0L, W1s[L],                      zpLA };
                ku.u[nu++] = KUnit{ h1L, W1s[L] + (size_t)256 * 1024, zpLB };
                uj.j[nj++] = UJob{ nullptr, zpLA, zpLB, b1s[L],
                                   c1L, h1L, LEN[L], Ts[L], i - 1 };
            }
        }
        if (nu > 0) {
            hgemm_kernel<<<dim3(32, nu), 256>>>(ku);
            lstm_gates_kernel<<<dim3(Bc, nj), 256>>>(uj);
        }
    }

    // output head
    final_kernel<<<Bc, 128>>>(h1_p + 0 * SB, h1_p + 1 * SB, h1_p + 2 * SB,
                              fW, fb, out);
}